// round 5
// baseline (speedup 1.0000x reference)
#include <cuda_runtime.h>
#include <cuda_fp16.h>
#include <cstdint>

#define DIN  4096
#define DOUT 4096
#define MROWS 8192   // 4 * 2048

// ---- GEMM tiling ----
#define BM 128
#define BN 256
#define BK 128                      // one weight-quant group per stage
#define NKI (DIN / BK)              // 32 k-iterations
#define NSTAGE 3
#define PITCH 144                   // 128B row + 16B pad -> conflict-free ldmatrix
#define A_BYTES (BM * PITCH)        // 18432
#define B_BYTES (BN * PITCH)        // 36864
#define STAGE_BYTES (A_BYTES + B_BYTES)              // 55296
#define WS_BYTES (32 * BN * 4)                       // 32768 (group scales, [g][n])
#define SMEM_TOTAL (NSTAGE * STAGE_BYTES + WS_BYTES) // 198656

// Scratch (device globals; no allocations allowed)
static __device__ __align__(128) int8_t g_qx8[(size_t)MROWS * DIN];  // 32 MB activations, exact int8
static __device__ __align__(128) int8_t g_wq8[(size_t)DOUT * DIN];   // 16 MB weights, exact (q-z) int
static __device__ float g_wsT[32 * DOUT];                            // group scales, transposed [g][n]
static __device__ float g_sa[MROWS];
static __device__ float g_scale[DIN];

// ------------------------------------------------------------------ helpers
__device__ __forceinline__ uint32_t smem_u32(const void* p) {
    uint32_t a;
    asm("{ .reg .u64 t; cvta.to.shared.u64 t, %1; cvt.u32.u64 %0, t; }" : "=r"(a) : "l"(p));
    return a;
}

#define CP16(dst, src) \
    asm volatile("cp.async.cg.shared.global [%0], [%1], 16;\n" :: "r"(dst), "l"(src))

// ---------------------------------------------------------------- scale
__global__ void scale_kernel(const float* __restrict__ log_scale) {
    int i = blockIdx.x * 256 + threadIdx.x;
    if (i < DIN) {
        float s = expf(log_scale[i]);
        g_scale[i] = fminf(fmaxf(s, 1e-4f), 1e4f);
    }
}

// ---------------------------------------------------------------- activation quant (per row, symmetric 8-bit)
__global__ void xquant_kernel(const float* __restrict__ x) {
    int row = blockIdx.x;
    const float* xr = x + (size_t)row * DIN;
    float v[16];
    float amax = 0.f;
#pragma unroll
    for (int j = 0; j < 16; j++) {
        int k = threadIdx.x + j * 256;
        v[j] = xr[k] / g_scale[k];
        amax = fmaxf(amax, fabsf(v[j]));
    }
#pragma unroll
    for (int o = 16; o > 0; o >>= 1)
        amax = fmaxf(amax, __shfl_xor_sync(0xffffffffu, amax, o));
    __shared__ float red[8];
    __shared__ float s_scale;
    if ((threadIdx.x & 31) == 0) red[threadIdx.x >> 5] = amax;
    __syncthreads();
    if (threadIdx.x == 0) {
        float m = red[0];
#pragma unroll
        for (int i = 1; i < 8; i++) m = fmaxf(m, red[i]);
        m = fmaxf(m, 1e-5f);
        float s = m / 127.f;
        s_scale = s;
        g_sa[row] = s;
    }
    __syncthreads();
    float s = s_scale;
    int8_t* q = g_qx8 + (size_t)row * DIN;
#pragma unroll
    for (int j = 0; j < 16; j++) {
        int k = threadIdx.x + j * 256;
        float t = rintf(v[j] / s);            // round-half-even matches jnp.round
        t = fminf(fmaxf(t, -128.f), 127.f);
        q[k] = (int8_t)(int)t;                // exact
    }
}

// ---------------------------------------------------------------- weight fake-quant (one warp per 128-group, 4-bit asym)
__global__ void wquant_kernel(const float* __restrict__ w) {
    int g = blockIdx.x * 8 + (threadIdx.x >> 5);
    int lane = threadIdx.x & 31;
    int row = g >> 5;          // D_OUT row
    int grp = g & 31;          // group within row
    const float* wr = w + (size_t)row * DIN + grp * 128;
    const float* sc = g_scale + grp * 128;
    float v[4];
    float mx = -3.4e38f, mn = 3.4e38f;
#pragma unroll
    for (int j = 0; j < 4; j++) {
        int k = lane + j * 32;
        v[j] = wr[k] * sc[k];
        mx = fmaxf(mx, v[j]);
        mn = fminf(mn, v[j]);
    }
#pragma unroll
    for (int o = 16; o > 0; o >>= 1) {
        mx = fmaxf(mx, __shfl_xor_sync(0xffffffffu, mx, o));
        mn = fminf(mn, __shfl_xor_sync(0xffffffffu, mn, o));
    }
    float s = fmaxf(mx - mn, 1e-5f) / 15.f;
    float z = fminf(fmaxf(-rintf(mn / s), 0.f), 15.f);
    int8_t* dst = g_wq8 + (size_t)row * DIN + grp * 128;
#pragma unroll
    for (int j = 0; j < 4; j++) {
        int k = lane + j * 32;
        float q = fminf(fmaxf(rintf(v[j] / s) + z, 0.f), 15.f);
        dst[k] = (int8_t)(int)(q - z);        // exact int in [-15,15]
    }
    if (lane == 0) g_wsT[(size_t)grp * DOUT + row] = s;
}

// ---------------------------------------------------------------- INT8 GEMM with per-group f32 merge
// out[m,n] = sa[m] * sum_g ws[g,n] * (sum_{k in g} qa*qw) + bias[n]
__global__ __launch_bounds__(512, 1) void gemm_kernel(const float* __restrict__ bias,
                                                      float* __restrict__ out) {
    extern __shared__ char smem[];
    const uint32_t sb = smem_u32(smem);
    const int tid  = threadIdx.x;
    const int warp = tid >> 5;
    const int lane = tid & 31;
    const int m0 = blockIdx.y * BM;
    const int n0 = blockIdx.x * BN;
    const int wm = (warp & 1) * 64;      // 2 M-warps
    const int wn = (warp >> 1) * 32;     // 8 N-warps

    const int8_t* gA = g_qx8 + (size_t)m0 * DIN;
    const int8_t* gB = g_wq8 + (size_t)n0 * DIN;
    float* ws_f = (float*)(smem + NSTAGE * STAGE_BYTES);

#define LOAD(S, KT)                                                               \
    {                                                                             \
        const int8_t* gak = gA + (size_t)(KT) * BK;                               \
        const int8_t* gbk = gB + (size_t)(KT) * BK;                               \
        uint32_t ab = sb + (S) * STAGE_BYTES;                                     \
        uint32_t bb = ab + A_BYTES;                                               \
        _Pragma("unroll")                                                         \
        for (int i = 0; i < 2; i++) {                                             \
            int id = tid + i * 512;                                               \
            int row = id >> 3, c = id & 7;                                        \
            CP16(ab + row * PITCH + c * 16, gak + (size_t)row * DIN + c * 16);    \
        }                                                                         \
        _Pragma("unroll")                                                         \
        for (int i = 0; i < 4; i++) {                                             \
            int id = tid + i * 512;                                               \
            int row = id >> 3, c = id & 7;                                        \
            CP16(bb + row * PITCH + c * 16, gbk + (size_t)row * DIN + c * 16);    \
        }                                                                         \
        asm volatile("cp.async.commit_group;" ::: "memory");                      \
    }

    LOAD(0, 0);
    LOAD(1, 1);

    // stage group scales ws[g][n-n0] into smem (coalesced from transposed global)
#pragma unroll
    for (int i = 0; i < 16; i++) {
        int idx = tid + i * 512;               // 32*256 = 8192
        int g = idx >> 8, nl = idx & 255;
        ws_f[idx] = g_wsT[(size_t)g * DOUT + n0 + nl];
    }

    float fac[4][4][4];
    int   sac[4][4][4];
#pragma unroll
    for (int a = 0; a < 4; a++)
#pragma unroll
        for (int b = 0; b < 4; b++)
#pragma unroll
            for (int c = 0; c < 4; c++) { fac[a][b][c] = 0.f; sac[a][b][c] = 0; }

    for (int kt = 0; kt < NKI; kt++) {
        if (kt <= NKI - 3)
            asm volatile("cp.async.wait_group 1;" ::: "memory");
        else
            asm volatile("cp.async.wait_group 0;" ::: "memory");
        __syncthreads();

        if (kt + 2 < NKI) LOAD((kt + 2) % NSTAGE, kt + 2);

        const uint32_t sA = sb + (kt % NSTAGE) * STAGE_BYTES;
        const uint32_t sB = sA + A_BYTES;

#pragma unroll
        for (int ks = 0; ks < 4; ks++) {          // 4 x k32 per stage
            uint32_t af[4][4];
#pragma unroll
            for (int mt = 0; mt < 4; mt++) {
                uint32_t addr = sA + (wm + mt * 16 + (lane & 15)) * PITCH
                              + ks * 32 + ((lane >> 4) << 4);
                asm volatile("ldmatrix.sync.aligned.m8n8.x4.shared.b16 {%0,%1,%2,%3}, [%4];\n"
                             : "=r"(af[mt][0]), "=r"(af[mt][1]),
                               "=r"(af[mt][2]), "=r"(af[mt][3])
                             : "r"(addr));
            }
            uint32_t bf[4][2];
#pragma unroll
            for (int nt = 0; nt < 4; nt++) {
                uint32_t addr = sB + (wn + nt * 8 + (lane & 7)) * PITCH
                              + ks * 32 + (((lane >> 3) & 1) << 4);
                asm volatile("ldmatrix.sync.aligned.m8n8.x2.shared.b16 {%0,%1}, [%2];\n"
                             : "=r"(bf[nt][0]), "=r"(bf[nt][1])
                             : "r"(addr));
            }
#pragma unroll
            for (int mt = 0; mt < 4; mt++)
#pragma unroll
                for (int nt = 0; nt < 4; nt++) {
                    asm volatile(
                        "mma.sync.aligned.m16n8k32.row.col.s32.s8.s8.s32 "
                        "{%0,%1,%2,%3}, {%4,%5,%6,%7}, {%8,%9}, {%0,%1,%2,%3};\n"
                        : "+r"(sac[mt][nt][0]), "+r"(sac[mt][nt][1]),
                          "+r"(sac[mt][nt][2]), "+r"(sac[mt][nt][3])
                        : "r"(af[mt][0]), "r"(af[mt][1]), "r"(af[mt][2]), "r"(af[mt][3]),
                          "r"(bf[nt][0]), "r"(bf[nt][1]));
                }
        }

        // group merge: fac += (float)sac * ws[g=kt][n], reset sac
        const float* wsg = ws_f + kt * BN + wn + ((lane & 3) << 1);
#pragma unroll
        for (int nt = 0; nt < 4; nt++) {
            float2 sw = *(const float2*)(wsg + nt * 8);
#pragma unroll
            for (int mt = 0; mt < 4; mt++) {
                fac[mt][nt][0] += (float)sac[mt][nt][0] * sw.x;
                fac[mt][nt][1] += (float)sac[mt][nt][1] * sw.y;
                fac[mt][nt][2] += (float)sac[mt][nt][2] * sw.x;
                fac[mt][nt][3] += (float)sac[mt][nt][3] * sw.y;
                sac[mt][nt][0] = 0; sac[mt][nt][1] = 0;
                sac[mt][nt][2] = 0; sac[mt][nt][3] = 0;
            }
        }
    }

    // ------------------------------------------------ epilogue: sa*acc + bias
#pragma unroll
    for (int mt = 0; mt < 4; mt++) {
        int r0 = m0 + wm + mt * 16 + (lane >> 2);
        float sa0 = g_sa[r0];
        float sa1 = g_sa[r0 + 8];
#pragma unroll
        for (int nt = 0; nt < 4; nt++) {
            int c0 = n0 + wn + nt * 8 + ((lane & 3) << 1);
            float2 b = *(const float2*)(bias + c0);
            float2 v0 = make_float2(fac[mt][nt][0] * sa0 + b.x,
                                    fac[mt][nt][1] * sa0 + b.y);
            float2 v1 = make_float2(fac[mt][nt][2] * sa1 + b.x,
                                    fac[mt][nt][3] * sa1 + b.y);
            *(float2*)(out + (size_t)r0 * DOUT + c0)       = v0;
            *(float2*)(out + (size_t)(r0 + 8) * DOUT + c0) = v1;
        }
    }
}

// ---------------------------------------------------------------- launch
extern "C" void kernel_launch(void* const* d_in, const int* in_sizes, int n_in,
                              void* d_out, int out_size) {
    const float* x    = (const float*)d_in[0];
    const float* w    = (const float*)d_in[1];
    const float* bias = (const float*)d_in[2];
    const float* lsc  = (const float*)d_in[3];
    float* out = (float*)d_out;

    cudaFuncSetAttribute(gemm_kernel, cudaFuncAttributeMaxDynamicSharedMemorySize, SMEM_TOTAL);

    scale_kernel<<<16, 256>>>(lsc);
    xquant_kernel<<<MROWS, 256>>>(x);
    wquant_kernel<<<(DOUT * 32) / 8, 256>>>(w);
    gemm_kernel<<<dim3(DOUT / BN, MROWS / BM), 512, SMEM_TOTAL>>>(bias, out);
}